// round 9
// baseline (speedup 1.0000x reference)
#include <cuda_runtime.h>
#include <cuda_bf16.h>
#include <cstdint>

#define BB 8
#define CC 64
#define CQ 8
#define NN 4096
#define KT 64
#define NTILES (NN / KT)
#define LOG2E 1.4426950408889634f

// Device scratch (allocation-free rule)
__device__ uint32_t g_Qt[BB * NN * CQ];         // [b][n][cq] tf32 bits, pre-scaled by log2e
__device__ uint32_t g_Kt[BB * NN * CQ];         // [b][n][cq] tf32 bits, plain channel order
__device__ __nv_bfloat16 g_Vb[BB * CC * NN];    // [b][c][n] bf16 (V^T)

// ---------------------------------------------------------------------------
// PTX helpers (baseline compute_103-safe: sm_80-era)
// ---------------------------------------------------------------------------
__device__ __forceinline__ uint32_t smem_u32(const void* p) {
    uint32_t a;
    asm("{ .reg .u64 t; cvta.to.shared.u64 t, %1; cvt.u32.u64 %0, t; }" : "=r"(a) : "l"(p));
    return a;
}
__device__ __forceinline__ uint32_t packbf(float lo, float hi) {
    uint32_t r;
    asm("cvt.rn.bf16x2.f32 %0, %1, %2;" : "=r"(r) : "f"(hi), "f"(lo));
    return r;
}
__device__ __forceinline__ uint32_t tf32c(float f) {
    uint32_t r;
    asm("cvt.rna.tf32.f32 %0, %1;" : "=r"(r) : "f"(f));
    return r;
}
__device__ __forceinline__ float ex2f(float x) {
    float y;
    asm("ex2.approx.f32 %0, %1;" : "=f"(y) : "f"(x));
    return y;
}
#define LDSM4(r0, r1, r2, r3, a) \
    asm volatile("ldmatrix.sync.aligned.m8n8.x4.shared.b16 {%0,%1,%2,%3}, [%4];" \
        : "=r"(r0), "=r"(r1), "=r"(r2), "=r"(r3) : "r"(a))
#define LDS64(r0, r1, a) \
    asm volatile("ld.shared.v2.u32 {%0,%1}, [%2];" : "=r"(r0), "=r"(r1) : "r"(a))
#define LDS32(r0, a) \
    asm volatile("ld.shared.u32 %0, [%1];" : "=r"(r0) : "r"(a))

#define CP_ASYNC16(dst, src) \
    asm volatile("cp.async.ca.shared.global [%0], [%1], 16;" :: "r"(dst), "l"(src) : "memory")
#define CP_COMMIT() asm volatile("cp.async.commit_group;" ::: "memory")
#define CP_WAIT0()  asm volatile("cp.async.wait_group 0;" ::: "memory")
#define CP_WAIT1()  asm volatile("cp.async.wait_group 1;" ::: "memory")

// m16n8k8 tf32 MMA, C = 0
#define MMAT32_Z(d, a0, a1, a2, a3, b0, b1) \
    asm volatile("mma.sync.aligned.m16n8k8.row.col.f32.tf32.tf32.f32 " \
        "{%0,%1,%2,%3}, {%4,%5,%6,%7}, {%8,%9}, {%10,%10,%10,%10};" \
        : "=f"((d)[0]), "=f"((d)[1]), "=f"((d)[2]), "=f"((d)[3]) \
        : "r"(a0), "r"(a1), "r"(a2), "r"(a3), "r"(b0), "r"(b1), "f"(0.f))
// m16n8k8 tf32 MMA, accumulate in place
#define MMAT32(d, a0, a1, a2, a3, b0, b1) \
    asm volatile("mma.sync.aligned.m16n8k8.row.col.f32.tf32.tf32.f32 " \
        "{%0,%1,%2,%3}, {%4,%5,%6,%7}, {%8,%9}, {%0,%1,%2,%3};" \
        : "+f"((d)[0]), "+f"((d)[1]), "+f"((d)[2]), "+f"((d)[3]) \
        : "r"(a0), "r"(a1), "r"(a2), "r"(a3), "r"(b0), "r"(b1))
// m16n8k16 bf16 MMA, accumulate in place
#define MMA16816(d, a0, a1, a2, a3, b0, b1) \
    asm volatile("mma.sync.aligned.m16n8k16.row.col.f32.bf16.bf16.f32 " \
        "{%0,%1,%2,%3}, {%4,%5,%6,%7}, {%8,%9}, {%0,%1,%2,%3};" \
        : "+f"((d)[0]), "+f"((d)[1]), "+f"((d)[2]), "+f"((d)[3]) \
        : "r"(a0), "r"(a1), "r"(a2), "r"(a3), "r"(b0), "r"(b1))

// ---------------------------------------------------------------------------
// Kernel 1: projections on tensor cores (tf32).
// CTA = 128 thr = 4 warps, 64 pixels. grid (64, 8) = 512 CTAs.
// GEMM: D[co][px] = W[co][ci] . x[ci][px], co-stack = [wv(64); wq(8); wk(8)].
// 5 m-tiles (4 V + 1 QK), 8 n-tiles of 8 px (2 per warp), 8 k-steps of 8 ci.
// Channel perm: MMA k-slot t4 / t4+4 <-> phys ci 2t4 / 2t4+1 (applied to both
// A and B fragments, so all storage stays in plain channel order).
// smem: x [64ci][64px] f32 rows padded to 272B (17408B) |
//       W [80 rows][64ci] f32 rows padded to 288B (23040B) = 40448B
// ---------------------------------------------------------------------------
__global__ void __launch_bounds__(128, 4) proj_kernel(
    const float* __restrict__ x,
    const float* __restrict__ wq, const float* __restrict__ bq,
    const float* __restrict__ wk, const float* __restrict__ bk,
    const float* __restrict__ wv, const float* __restrict__ bv)
{
    __shared__ __align__(16) char sx[64 * 272];
    __shared__ __align__(16) char sw[80 * 288];

    const int tid  = threadIdx.x;
    const int lane = tid & 31;
    const int w    = tid >> 5;
    const int g    = lane >> 2;
    const int t4   = lane & 3;
    const int b    = blockIdx.y;
    const int n0   = blockIdx.x * 64;

    const uint32_t sxb = smem_u32(sx);
    const uint32_t swb = smem_u32(sw);

    // Stage x tile [64ci][64px] (1024 x 16B chunks, 8 per thread)
    const float* xb = x + (size_t)b * CC * NN + n0;
    #pragma unroll
    for (int i = 0; i < 8; ++i) {
        const int c = i * 128 + tid;
        const int row = c >> 4, off = c & 15;
        CP_ASYNC16(sxb + row * 272 + off * 16, xb + (size_t)row * NN + off * 4);
    }
    // Stage wv rows 0..63 (1024 chunks, 8/thread)
    #pragma unroll
    for (int i = 0; i < 8; ++i) {
        const int c = i * 128 + tid;
        const int row = c >> 4, off = c & 15;
        CP_ASYNC16(swb + row * 288 + off * 16, wv + row * 64 + off * 4);
    }
    // Stage wq -> rows 64..71, wk -> rows 72..79 (128 chunks each)
    {
        const int row = tid >> 4, off = tid & 15;
        CP_ASYNC16(swb + (64 + row) * 288 + off * 16, wq + row * 64 + off * 4);
        CP_ASYNC16(swb + (72 + row) * 288 + off * 16, wk + row * 64 + off * 4);
    }
    CP_COMMIT();

    // Accumulators: [nt2][mt][4], init with bias (d0,d1 = row g; d2,d3 = row g+8)
    float acc[2][5][4];
    #pragma unroll
    for (int mt = 0; mt < 4; ++mt) {
        const float bA = __ldg(bv + mt * 16 + g);
        const float bB = __ldg(bv + mt * 16 + 8 + g);
        #pragma unroll
        for (int n2 = 0; n2 < 2; ++n2) {
            acc[n2][mt][0] = bA; acc[n2][mt][1] = bA;
            acc[n2][mt][2] = bB; acc[n2][mt][3] = bB;
        }
    }
    {
        const float bA = __ldg(bq + g);
        const float bB = __ldg(bk + g);
        #pragma unroll
        for (int n2 = 0; n2 < 2; ++n2) {
            acc[n2][4][0] = bA; acc[n2][4][1] = bA;
            acc[n2][4][2] = bB; acc[n2][4][3] = bB;
        }
    }

    CP_WAIT0();
    __syncthreads();

    // Main GEMM: 8 k-steps x (5 m-tiles x 2 n-tiles)
    const uint32_t waddr0 = swb + (uint32_t)g * 288 + (uint32_t)t4 * 8;   // row g, ci pair
    const uint32_t xaddr0 = sxb + (uint32_t)(2 * t4) * 272
                          + (uint32_t)((w * 2) * 8 + g) * 4;              // ci 2t4, px
    #pragma unroll
    for (int kt = 0; kt < 8; ++kt) {
        uint32_t wa[5][4];
        #pragma unroll
        for (int mt = 0; mt < 5; ++mt) {
            LDS64(wa[mt][0], wa[mt][2], waddr0 + (uint32_t)(mt * 16) * 288 + kt * 32);
            LDS64(wa[mt][1], wa[mt][3], waddr0 + (uint32_t)(mt * 16 + 8) * 288 + kt * 32);
        }
        #pragma unroll
        for (int mt = 0; mt < 5; ++mt) {
            #pragma unroll
            for (int e = 0; e < 4; ++e) wa[mt][e] = tf32c(__uint_as_float(wa[mt][e]));
        }
        #pragma unroll
        for (int n2 = 0; n2 < 2; ++n2) {
            uint32_t b0, b1;
            LDS32(b0, xaddr0 + kt * (8 * 272) + n2 * 32);
            LDS32(b1, xaddr0 + kt * (8 * 272) + n2 * 32 + 272);
            b0 = tf32c(__uint_as_float(b0));
            b1 = tf32c(__uint_as_float(b1));
            #pragma unroll
            for (int mt = 0; mt < 5; ++mt)
                MMAT32(acc[n2][mt], wa[mt][0], wa[mt][1], wa[mt][2], wa[mt][3], b0, b1);
        }
    }

    // Epilogue: write V (bf16x2 packed), Q (tf32 bits x log2e), K (tf32 bits)
    #pragma unroll
    for (int n2 = 0; n2 < 2; ++n2) {
        const int px = (w * 2 + n2) * 8 + 2 * t4;     // global px pair (px, px+1)
        // V: 4 m-tiles
        #pragma unroll
        for (int mt = 0; mt < 4; ++mt) {
            const int coA = mt * 16 + g;
            const int coB = coA + 8;
            *(uint32_t*)(g_Vb + (size_t)b * CC * NN + (size_t)coA * NN + n0 + px) =
                packbf(acc[n2][mt][0], acc[n2][mt][1]);
            *(uint32_t*)(g_Vb + (size_t)b * CC * NN + (size_t)coB * NN + n0 + px) =
                packbf(acc[n2][mt][2], acc[n2][mt][3]);
        }
        // Q (rows g of QK tile), K (rows g+8)
        const size_t qk0 = ((size_t)b * NN + n0 + px) * CQ + g;
        g_Qt[qk0]      = tf32c(acc[n2][4][0] * LOG2E);
        g_Qt[qk0 + CQ] = tf32c(acc[n2][4][1] * LOG2E);
        g_Kt[qk0]      = tf32c(acc[n2][4][2]);
        g_Kt[qk0 + CQ] = tf32c(acc[n2][4][3]);
    }
}

// ---------------------------------------------------------------------------
// Kernel 2: tensorized fused attention (round-8 skeleton; Q/K now plain order,
// Q pre-converted to tf32 bits).
// Block = 128 thr = 4 warps x 16 query rows. grid (64, 8) = 512 CTAs.
// smem: K 3 stages x 2KB (6KB) | V 3 stages x 8KB (24KB) = 30 KB.
// ---------------------------------------------------------------------------
__global__ void __launch_bounds__(128, 4) attn_kernel(float* __restrict__ out)
{
    __shared__ __align__(16) char smraw[6144 + 3 * 8192];

    const int tid  = threadIdx.x;
    const int lane = tid & 31;
    const int w    = tid >> 5;
    const int g    = lane >> 2;
    const int t4   = lane & 3;
    const int b    = blockIdx.y;
    const int ibase = blockIdx.x * 64 + w * 16;

    const uint32_t smb = smem_u32(smraw);

    // Q A-fragment (tf32 bits, channel perm: slots t4/t4+4 = phys 2t4/2t4+1)
    const uint32_t* Qb = g_Qt + (size_t)b * NN * CQ;
    const uint32_t* q0p = Qb + (size_t)(ibase + g) * CQ + 2 * t4;
    const uint32_t* q1p = Qb + (size_t)(ibase + g + 8) * CQ + 2 * t4;
    const uint32_t qa0 = q0p[0];
    const uint32_t qa2 = q0p[1];
    const uint32_t qa1 = q1p[0];
    const uint32_t qa3 = q1p[1];

    // K staging: 128 threads x 16B = 2KB/tile (thread = half a key)
    const uint32_t* Ksrc = g_Kt + (size_t)b * NN * CQ + (size_t)(tid >> 1) * 8 + (tid & 1) * 4;
    const uint32_t kdst = smb + (uint32_t)(tid >> 1) * 32 + (uint32_t)(tid & 1) * 16;

    // V staging: 4 x 16B per tile, xor-swizzled rows (V region at +6144)
    const char* Vgb = (const char*)(g_Vb + (size_t)b * CC * NN);
    const uint32_t voff0 = (uint32_t)(tid >> 3) * (NN * 2) + (uint32_t)(tid & 7) * 16;
    const uint32_t vdst0 = smb + 6144 + (uint32_t)(tid >> 3) * 128
                         + (uint32_t)(((tid & 7) ^ ((tid >> 3) & 7)) << 4);

    // Score B-fragment LDS: key = lane>>2, chans (2t4, 2t4+1) = bytes t4*8
    const uint32_t kfrag0 = smb + (uint32_t)(lane >> 2) * 32 + (uint32_t)t4 * 8;

    // V ldmatrix addresses
    const int mat = lane >> 3, mrow = lane & 7, m01 = mat & 1;
    const uint32_t vbase0 = smb + 6144 + (uint32_t)((mat >> 1) * 8 + mrow) * 128;

    // Prologue: tiles 0, 1 (one commit group per tile)
    #pragma unroll
    for (int t = 0; t < 2; ++t) {
        CP_ASYNC16(kdst + t * 2048, Ksrc + (size_t)t * KT * CQ);
        #pragma unroll
        for (int r = 0; r < 4; ++r)
            CP_ASYNC16(vdst0 + r * 2048 + t * 8192, Vgb + voff0 + r * 131072 + t * 128);
        CP_COMMIT();
    }

    float acc[8][4];
    #pragma unroll
    for (int nb = 0; nb < 8; ++nb)
        #pragma unroll
        for (int e = 0; e < 4; ++e) acc[nb][e] = 0.f;
    float lsum0 = 0.f, lsum1 = 0.f;
    uint32_t ksoff = 0, vsoff = 0;

    #pragma unroll 1
    for (int t = 0; t < NTILES; ++t) {
        CP_WAIT1();             // tile t landed
        __syncthreads();        // ...visible to all; stage t-1 fully consumed

        // Prefetch tile t+2 into stage (t+2)%3
        {
            const int tc = t + 2;
            uint32_t ks2 = ksoff + 4096;  if (ks2 >= 6144)  ks2 -= 6144;
            uint32_t vs2 = vsoff + 16384; if (vs2 >= 24576) vs2 -= 24576;
            if (tc < NTILES) {
                CP_ASYNC16(kdst + ks2, Ksrc + (size_t)tc * KT * CQ);
                #pragma unroll
                for (int r = 0; r < 4; ++r)
                    CP_ASYNC16(vdst0 + r * 2048 + vs2,
                               Vgb + voff0 + r * 131072 + (size_t)tc * 128);
            }
            CP_COMMIT();        // always commit to keep group arithmetic
        }

        #pragma unroll
        for (int kt = 0; kt < 4; ++kt) {
            // scores for n-tiles 2kt, 2kt+1 (8 keys each): 1 tf32 MMA each
            uint32_t b00, b01, b10, b11;
            LDS64(b00, b01, kfrag0 + ksoff + (uint32_t)(2 * kt) * 256);
            LDS64(b10, b11, kfrag0 + ksoff + (uint32_t)(2 * kt) * 256 + 256);
            float p0[4], p1[4];
            MMAT32_Z(p0, qa0, qa1, qa2, qa3, b00, b01);
            MMAT32_Z(p1, qa0, qa1, qa2, qa3, b10, b11);

            #pragma unroll
            for (int e = 0; e < 4; ++e) { p0[e] = ex2f(p0[e]); p1[e] = ex2f(p1[e]); }
            lsum0 += (p0[0] + p0[1]) + (p1[0] + p1[1]);
            lsum1 += (p0[2] + p0[3]) + (p1[2] + p1[3]);

            const uint32_t a0 = packbf(p0[0], p0[1]);
            const uint32_t a1 = packbf(p0[2], p0[3]);
            const uint32_t a2 = packbf(p1[0], p1[1]);
            const uint32_t a3 = packbf(p1[2], p1[3]);

            const uint32_t term = ((uint32_t)((2 * kt + m01) ^ mrow)) << 4;
            uint32_t vb[16];
            #pragma unroll
            for (int c = 0; c < 4; ++c)
                LDSM4(vb[4 * c + 0], vb[4 * c + 1], vb[4 * c + 2], vb[4 * c + 3],
                      vbase0 + vsoff + c * 2048 + term);
            #pragma unroll
            for (int nb = 0; nb < 8; ++nb)
                MMA16816(acc[nb], a0, a1, a2, a3, vb[2 * nb], vb[2 * nb + 1]);
        }

        ksoff += 2048; if (ksoff == 6144)  ksoff = 0;
        vsoff += 8192; if (vsoff == 24576) vsoff = 0;
    }

    // l: reduce over the 4 lanes of each quad
    lsum0 += __shfl_xor_sync(0xFFFFFFFFu, lsum0, 1);
    lsum0 += __shfl_xor_sync(0xFFFFFFFFu, lsum0, 2);
    lsum1 += __shfl_xor_sync(0xFFFFFFFFu, lsum1, 1);
    lsum1 += __shfl_xor_sync(0xFFFFFFFFu, lsum1, 2);
    const float invA = 1.f / lsum0;
    const float invB = 1.f / lsum1;

    float* outb = out + (size_t)b * CC * NN;
    const int rA = ibase + g;
    const int rB = rA + 8;
    #pragma unroll
    for (int nb = 0; nb < 8; ++nb) {
        const int c = nb * 8 + 2 * t4;
        outb[(size_t)c * NN + rA]       = acc[nb][0] * invA;
        outb[(size_t)(c + 1) * NN + rA] = acc[nb][1] * invA;
        outb[(size_t)c * NN + rB]       = acc[nb][2] * invB;
        outb[(size_t)(c + 1) * NN + rB] = acc[nb][3] * invB;
    }
}

// ---------------------------------------------------------------------------
extern "C" void kernel_launch(void* const* d_in, const int* in_sizes, int n_in,
                              void* d_out, int out_size)
{
    const float* x  = (const float*)d_in[0];
    const float* wq = (const float*)d_in[1];
    const float* bq = (const float*)d_in[2];
    const float* wk = (const float*)d_in[3];
    const float* bk = (const float*)d_in[4];
    const float* wv = (const float*)d_in[5];
    const float* bv = (const float*)d_in[6];
    float* out = (float*)d_out;

    dim3 pgrid(NN / 64, BB);
    proj_kernel<<<pgrid, 128>>>(x, wq, bq, wk, bk, wv, bv);

    dim3 agrid(NN / 64, BB);
    attn_kernel<<<agrid, 128>>>(out);
}

// round 10
// speedup vs baseline: 1.5611x; 1.5611x over previous
#include <cuda_runtime.h>
#include <cuda_bf16.h>
#include <cstdint>

#define BB 8
#define CC 64
#define CQ 8
#define NN 4096
#define KT 64
#define NTILES (NN / KT)
#define LOG2E 1.4426950408889634f

// Device scratch (allocation-free rule)
__device__ float    g_Q[BB * NN * CQ];          // [b][n][cq] f32, pre-scaled by log2e
__device__ uint32_t g_Kt[BB * NN * CQ];         // [b][n]: 8 tf32 bits, pair-permuted (c,c+4)
__device__ __nv_bfloat16 g_Vb[BB * CC * NN];    // [b][c][n] bf16 (V^T)

// ---------------------------------------------------------------------------
// PTX helpers (baseline compute_103-safe: sm_80-era)
// ---------------------------------------------------------------------------
__device__ __forceinline__ uint32_t smem_u32(const void* p) {
    uint32_t a;
    asm("{ .reg .u64 t; cvta.to.shared.u64 t, %1; cvt.u32.u64 %0, t; }" : "=r"(a) : "l"(p));
    return a;
}
__device__ __forceinline__ uint32_t packbf(float lo, float hi) {
    uint32_t r;
    asm("cvt.rn.bf16x2.f32 %0, %1, %2;" : "=r"(r) : "f"(hi), "f"(lo));
    return r;
}
__device__ __forceinline__ uint32_t tf32c(float f) {
    uint32_t r;
    asm("cvt.rna.tf32.f32 %0, %1;" : "=r"(r) : "f"(f));
    return r;
}
__device__ __forceinline__ float ex2f(float x) {
    float y;
    asm("ex2.approx.f32 %0, %1;" : "=f"(y) : "f"(x));
    return y;
}
#define LDSM4(r0, r1, r2, r3, a) \
    asm volatile("ldmatrix.sync.aligned.m8n8.x4.shared.b16 {%0,%1,%2,%3}, [%4];" \
        : "=r"(r0), "=r"(r1), "=r"(r2), "=r"(r3) : "r"(a))
#define LDS64(r0, r1, a) \
    asm volatile("ld.shared.v2.u32 {%0,%1}, [%2];" : "=r"(r0), "=r"(r1) : "r"(a))
#define LDS32(r0, a) \
    asm volatile("ld.shared.u32 %0, [%1];" : "=r"(r0) : "r"(a))

#define CP_ASYNC16(dst, src) \
    asm volatile("cp.async.ca.shared.global [%0], [%1], 16;" :: "r"(dst), "l"(src) : "memory")
#define CP_COMMIT() asm volatile("cp.async.commit_group;" ::: "memory")
#define CP_WAIT0()  asm volatile("cp.async.wait_group 0;" ::: "memory")
#define CP_WAIT1()  asm volatile("cp.async.wait_group 1;" ::: "memory")

// m16n8k8 tf32 MMA, C = 0
#define MMAT32_Z(d, a0, a1, a2, a3, b0, b1) \
    asm volatile("mma.sync.aligned.m16n8k8.row.col.f32.tf32.tf32.f32 " \
        "{%0,%1,%2,%3}, {%4,%5,%6,%7}, {%8,%9}, {%10,%10,%10,%10};" \
        : "=f"((d)[0]), "=f"((d)[1]), "=f"((d)[2]), "=f"((d)[3]) \
        : "r"(a0), "r"(a1), "r"(a2), "r"(a3), "r"(b0), "r"(b1), "f"(0.f))
// m16n8k8 tf32 MMA, accumulate in place
#define MMAT32(d, a0, a1, a2, a3, b0, b1) \
    asm volatile("mma.sync.aligned.m16n8k8.row.col.f32.tf32.tf32.f32 " \
        "{%0,%1,%2,%3}, {%4,%5,%6,%7}, {%8,%9}, {%0,%1,%2,%3};" \
        : "+f"((d)[0]), "+f"((d)[1]), "+f"((d)[2]), "+f"((d)[3]) \
        : "r"(a0), "r"(a1), "r"(a2), "r"(a3), "r"(b0), "r"(b1))
// m16n8k16 bf16 MMA, accumulate in place
#define MMA16816(d, a0, a1, a2, a3, b0, b1) \
    asm volatile("mma.sync.aligned.m16n8k16.row.col.f32.bf16.bf16.f32 " \
        "{%0,%1,%2,%3}, {%4,%5,%6,%7}, {%8,%9}, {%0,%1,%2,%3};" \
        : "+f"((d)[0]), "+f"((d)[1]), "+f"((d)[2]), "+f"((d)[3]) \
        : "r"(a0), "r"(a1), "r"(a2), "r"(a3), "r"(b0), "r"(b1))

// ---------------------------------------------------------------------------
// Kernel 1: projections on tensor cores (tf32), round-9 core.
// Epilogue retargeted to ROUND-8 data formats:
//   Q plain-order f32 (x log2e), K pair-permuted tf32 bits, V bf16 [c][n].
// ---------------------------------------------------------------------------
__global__ void __launch_bounds__(128, 4) proj_kernel(
    const float* __restrict__ x,
    const float* __restrict__ wq, const float* __restrict__ bq,
    const float* __restrict__ wk, const float* __restrict__ bk,
    const float* __restrict__ wv, const float* __restrict__ bv)
{
    __shared__ __align__(16) char sx[64 * 272];
    __shared__ __align__(16) char sw[80 * 288];

    const int tid  = threadIdx.x;
    const int lane = tid & 31;
    const int w    = tid >> 5;
    const int g    = lane >> 2;
    const int t4   = lane & 3;
    const int b    = blockIdx.y;
    const int n0   = blockIdx.x * 64;

    const uint32_t sxb = smem_u32(sx);
    const uint32_t swb = smem_u32(sw);

    // Stage x tile [64ci][64px]
    const float* xb = x + (size_t)b * CC * NN + n0;
    #pragma unroll
    for (int i = 0; i < 8; ++i) {
        const int c = i * 128 + tid;
        const int row = c >> 4, off = c & 15;
        CP_ASYNC16(sxb + row * 272 + off * 16, xb + (size_t)row * NN + off * 4);
    }
    // Stage wv rows 0..63
    #pragma unroll
    for (int i = 0; i < 8; ++i) {
        const int c = i * 128 + tid;
        const int row = c >> 4, off = c & 15;
        CP_ASYNC16(swb + row * 288 + off * 16, wv + row * 64 + off * 4);
    }
    // Stage wq -> rows 64..71, wk -> rows 72..79
    {
        const int row = tid >> 4, off = tid & 15;
        CP_ASYNC16(swb + (64 + row) * 288 + off * 16, wq + row * 64 + off * 4);
        CP_ASYNC16(swb + (72 + row) * 288 + off * 16, wk + row * 64 + off * 4);
    }
    CP_COMMIT();

    // Accumulators init with bias
    float acc[2][5][4];
    #pragma unroll
    for (int mt = 0; mt < 4; ++mt) {
        const float bA = __ldg(bv + mt * 16 + g);
        const float bB = __ldg(bv + mt * 16 + 8 + g);
        #pragma unroll
        for (int n2 = 0; n2 < 2; ++n2) {
            acc[n2][mt][0] = bA; acc[n2][mt][1] = bA;
            acc[n2][mt][2] = bB; acc[n2][mt][3] = bB;
        }
    }
    {
        const float bA = __ldg(bq + g);
        const float bB = __ldg(bk + g);
        #pragma unroll
        for (int n2 = 0; n2 < 2; ++n2) {
            acc[n2][4][0] = bA; acc[n2][4][1] = bA;
            acc[n2][4][2] = bB; acc[n2][4][3] = bB;
        }
    }

    CP_WAIT0();
    __syncthreads();

    // Main GEMM: 8 k-steps x (5 m-tiles x 2 n-tiles)
    const uint32_t waddr0 = swb + (uint32_t)g * 288 + (uint32_t)t4 * 8;
    const uint32_t xaddr0 = sxb + (uint32_t)(2 * t4) * 272
                          + (uint32_t)((w * 2) * 8 + g) * 4;
    #pragma unroll
    for (int kt = 0; kt < 8; ++kt) {
        uint32_t wa[5][4];
        #pragma unroll
        for (int mt = 0; mt < 5; ++mt) {
            LDS64(wa[mt][0], wa[mt][2], waddr0 + (uint32_t)(mt * 16) * 288 + kt * 32);
            LDS64(wa[mt][1], wa[mt][3], waddr0 + (uint32_t)(mt * 16 + 8) * 288 + kt * 32);
        }
        #pragma unroll
        for (int mt = 0; mt < 5; ++mt) {
            #pragma unroll
            for (int e = 0; e < 4; ++e) wa[mt][e] = tf32c(__uint_as_float(wa[mt][e]));
        }
        #pragma unroll
        for (int n2 = 0; n2 < 2; ++n2) {
            uint32_t b0, b1;
            LDS32(b0, xaddr0 + kt * (8 * 272) + n2 * 32);
            LDS32(b1, xaddr0 + kt * (8 * 272) + n2 * 32 + 272);
            b0 = tf32c(__uint_as_float(b0));
            b1 = tf32c(__uint_as_float(b1));
            #pragma unroll
            for (int mt = 0; mt < 5; ++mt)
                MMAT32(acc[n2][mt], wa[mt][0], wa[mt][1], wa[mt][2], wa[mt][3], b0, b1);
        }
    }

    // Epilogue (round-8 formats)
    const int kslot = 2 * (g & 3) + (g >> 2);         // pair-permute position of chan g
    #pragma unroll
    for (int n2 = 0; n2 < 2; ++n2) {
        const int px = (w * 2 + n2) * 8 + 2 * t4;     // pixel pair (px, px+1)
        // V: bf16x2 packed into [c][n]
        #pragma unroll
        for (int mt = 0; mt < 4; ++mt) {
            const int coA = mt * 16 + g;
            const int coB = coA + 8;
            *(uint32_t*)(g_Vb + (size_t)b * CC * NN + (size_t)coA * NN + n0 + px) =
                packbf(acc[n2][mt][0], acc[n2][mt][1]);
            *(uint32_t*)(g_Vb + (size_t)b * CC * NN + (size_t)coB * NN + n0 + px) =
                packbf(acc[n2][mt][2], acc[n2][mt][3]);
        }
        // Q: plain-order f32 x log2e;  K: pair-permuted tf32 bits
        const size_t base0 = ((size_t)b * NN + n0 + px) * CQ;
        const size_t base1 = base0 + CQ;
        g_Q[base0 + g] = acc[n2][4][0] * LOG2E;
        g_Q[base1 + g] = acc[n2][4][1] * LOG2E;
        g_Kt[base0 + kslot] = tf32c(acc[n2][4][2]);
        g_Kt[base1 + kslot] = tf32c(acc[n2][4][3]);
    }
}

// ---------------------------------------------------------------------------
// Kernel 2: tensorized fused attention — ROUND-8 KERNEL VERBATIM.
// Block = 128 thr = 4 warps x 16 query rows. grid (64, 8) = 512 CTAs.
// smem: K 3 stages x 2KB (6KB) | V 3 stages x 8KB (24KB) = 30 KB.
// ---------------------------------------------------------------------------
__global__ void __launch_bounds__(128, 4) attn_kernel(float* __restrict__ out)
{
    __shared__ __align__(16) char smraw[6144 + 3 * 8192];

    const int tid  = threadIdx.x;
    const int lane = tid & 31;
    const int w    = tid >> 5;
    const int g    = lane >> 2;
    const int t4   = lane & 3;
    const int b    = blockIdx.y;
    const int ibase = blockIdx.x * 64 + w * 16;

    const uint32_t smb = smem_u32(smraw);

    // Q A-fragment (m16n8k8 tf32): a0=(g,t4) a1=(g+8,t4) a2=(g,t4+4) a3=(g+8,t4+4)
    const float* Qb = g_Q + (size_t)b * NN * CQ;
    const float* q0p = Qb + (size_t)(ibase + g) * CQ;
    const float* q1p = Qb + (size_t)(ibase + g + 8) * CQ;
    const uint32_t qa0 = tf32c(q0p[t4]);
    const uint32_t qa1 = tf32c(q1p[t4]);
    const uint32_t qa2 = tf32c(q0p[t4 + 4]);
    const uint32_t qa3 = tf32c(q1p[t4 + 4]);

    // K staging: 128 threads x 16B = 2KB/tile (thread = half a key)
    const uint32_t* Ksrc = g_Kt + (size_t)b * NN * CQ + (size_t)(tid >> 1) * 8 + (tid & 1) * 4;
    const uint32_t kdst = smb + (uint32_t)(tid >> 1) * 32 + (uint32_t)(tid & 1) * 16;

    // V staging: 4 x 16B per tile, xor-swizzled rows (V region at +6144)
    const char* Vgb = (const char*)(g_Vb + (size_t)b * CC * NN);
    const uint32_t voff0 = (uint32_t)(tid >> 3) * (NN * 2) + (uint32_t)(tid & 7) * 16;
    const uint32_t vdst0 = smb + 6144 + (uint32_t)(tid >> 3) * 128
                         + (uint32_t)(((tid & 7) ^ ((tid >> 3) & 7)) << 4);

    // Score B-fragment LDS address: key = lane>>2 within n-tile, chans (t4, t4+4)
    const uint32_t kfrag0 = smb + (uint32_t)(lane >> 2) * 32 + (uint32_t)t4 * 8;

    // V ldmatrix addresses
    const int mat = lane >> 3, mrow = lane & 7, m01 = mat & 1;
    const uint32_t vbase0 = smb + 6144 + (uint32_t)((mat >> 1) * 8 + mrow) * 128;

    // Prologue: tiles 0, 1 (one commit group per tile: K then V)
    #pragma unroll
    for (int t = 0; t < 2; ++t) {
        CP_ASYNC16(kdst + t * 2048, Ksrc + (size_t)t * KT * CQ);
        #pragma unroll
        for (int r = 0; r < 4; ++r)
            CP_ASYNC16(vdst0 + r * 2048 + t * 8192, Vgb + voff0 + r * 131072 + t * 128);
        CP_COMMIT();
    }

    float acc[8][4];
    #pragma unroll
    for (int nb = 0; nb < 8; ++nb)
        #pragma unroll
        for (int e = 0; e < 4; ++e) acc[nb][e] = 0.f;
    float lsum0 = 0.f, lsum1 = 0.f;
    uint32_t ksoff = 0, vsoff = 0;

    #pragma unroll 1
    for (int t = 0; t < NTILES; ++t) {
        CP_WAIT1();             // tile t landed
        __syncthreads();        // ...visible to all; stage t-1 fully consumed

        // Prefetch tile t+2 into stage (t+2)%3
        {
            const int tc = t + 2;
            uint32_t ks2 = ksoff + 4096;  if (ks2 >= 6144)  ks2 -= 6144;
            uint32_t vs2 = vsoff + 16384; if (vs2 >= 24576) vs2 -= 24576;
            if (tc < NTILES) {
                CP_ASYNC16(kdst + ks2, Ksrc + (size_t)tc * KT * CQ);
                #pragma unroll
                for (int r = 0; r < 4; ++r)
                    CP_ASYNC16(vdst0 + r * 2048 + vs2,
                               Vgb + voff0 + r * 131072 + (size_t)tc * 128);
            }
            CP_COMMIT();        // always commit to keep group arithmetic
        }

        #pragma unroll
        for (int kt = 0; kt < 4; ++kt) {
            // scores for n-tiles 2kt, 2kt+1 (8 keys each): 1 tf32 MMA each
            uint32_t b00, b01, b10, b11;
            LDS64(b00, b01, kfrag0 + ksoff + (uint32_t)(2 * kt) * 256);
            LDS64(b10, b11, kfrag0 + ksoff + (uint32_t)(2 * kt) * 256 + 256);
            float p0[4], p1[4];
            MMAT32_Z(p0, qa0, qa1, qa2, qa3, b00, b01);
            MMAT32_Z(p1, qa0, qa1, qa2, qa3, b10, b11);

            #pragma unroll
            for (int e = 0; e < 4; ++e) { p0[e] = ex2f(p0[e]); p1[e] = ex2f(p1[e]); }
            lsum0 += (p0[0] + p0[1]) + (p1[0] + p1[1]);
            lsum1 += (p0[2] + p0[3]) + (p1[2] + p1[3]);

            const uint32_t a0 = packbf(p0[0], p0[1]);
            const uint32_t a1 = packbf(p0[2], p0[3]);
            const uint32_t a2 = packbf(p1[0], p1[1]);
            const uint32_t a3 = packbf(p1[2], p1[3]);

            const uint32_t term = ((uint32_t)((2 * kt + m01) ^ mrow)) << 4;
            uint32_t vb[16];
            #pragma unroll
            for (int c = 0; c < 4; ++c)
                LDSM4(vb[4 * c + 0], vb[4 * c + 1], vb[4 * c + 2], vb[4 * c + 3],
                      vbase0 + vsoff + c * 2048 + term);
            #pragma unroll
            for (int nb = 0; nb < 8; ++nb)
                MMA16816(acc[nb], a0, a1, a2, a3, vb[2 * nb], vb[2 * nb + 1]);
        }

        ksoff += 2048; if (ksoff == 6144)  ksoff = 0;
        vsoff += 8192; if (vsoff == 24576) vsoff = 0;
    }

    // l: reduce over the 4 lanes of each quad
    lsum0 += __shfl_xor_sync(0xFFFFFFFFu, lsum0, 1);
    lsum0 += __shfl_xor_sync(0xFFFFFFFFu, lsum0, 2);
    lsum1 += __shfl_xor_sync(0xFFFFFFFFu, lsum1, 1);
    lsum1 += __shfl_xor_sync(0xFFFFFFFFu, lsum1, 2);
    const float invA = 1.f / lsum0;
    const float invB = 1.f / lsum1;

    float* outb = out + (size_t)b * CC * NN;
    const int rA = ibase + g;
    const int rB = rA + 8;
    #pragma unroll
    for (int nb = 0; nb < 8; ++nb) {
        const int c = nb * 8 + 2 * t4;
        outb[(size_t)c * NN + rA]       = acc[nb][0] * invA;
        outb[(size_t)(c + 1) * NN + rA] = acc[nb][1] * invA;
        outb[(size_t)c * NN + rB]       = acc[nb][2] * invB;
        outb[(size_t)(c + 1) * NN + rB] = acc[nb][3] * invB;
    }
}

// ---------------------------------------------------------------------------
extern "C" void kernel_launch(void* const* d_in, const int* in_sizes, int n_in,
                              void* d_out, int out_size)
{
    const float* x  = (const float*)d_in[0];
    const float* wq = (const float*)d_in[1];
    const float* bq = (const float*)d_in[2];
    const float* wk = (const float*)d_in[3];
    const float* bk = (const float*)d_in[4];
    const float* wv = (const float*)d_in[5];
    const float* bv = (const float*)d_in[6];
    float* out = (float*)d_out;

    dim3 pgrid(NN / 64, BB);
    proj_kernel<<<pgrid, 128>>>(x, wq, bq, wk, bk, wv, bv);

    dim3 agrid(NN / 64, BB);
    attn_kernel<<<agrid, 128>>>(out);
}

// round 11
// speedup vs baseline: 1.6846x; 1.0791x over previous
#include <cuda_runtime.h>
#include <cuda_bf16.h>
#include <cstdint>

#define BB 8
#define CC 64
#define CQ 8
#define NN 4096
#define KT 64
#define NSPLIT 4
#define KEYS_PER_SPLIT (NN / NSPLIT)          // 1024
#define TILES_PER_SPLIT (KEYS_PER_SPLIT / KT) // 16
#define LOG2E 1.4426950408889634f

// Device scratch (allocation-free rule)
__device__ float    g_Q[BB * NN * CQ];          // [b][n][cq] f32, pre-scaled by log2e
__device__ uint32_t g_Kt[BB * NN * CQ];         // [b][n]: 8 tf32 bits, pair-permuted (c,c+4)
__device__ __nv_bfloat16 g_Vb[BB * CC * NN];    // [b][c][n] bf16 (V^T)
__device__ float    g_P[NSPLIT * BB * CC * NN]; // [s][b][c][i] unnormalized partials (32MB)
__device__ float    g_L[NSPLIT * BB * NN];      // [s][b][i] partial row sums

// ---------------------------------------------------------------------------
// PTX helpers (baseline compute_103-safe: sm_80-era)
// ---------------------------------------------------------------------------
__device__ __forceinline__ uint32_t smem_u32(const void* p) {
    uint32_t a;
    asm("{ .reg .u64 t; cvta.to.shared.u64 t, %1; cvt.u32.u64 %0, t; }" : "=r"(a) : "l"(p));
    return a;
}
__device__ __forceinline__ uint32_t packbf(float lo, float hi) {
    uint32_t r;
    asm("cvt.rn.bf16x2.f32 %0, %1, %2;" : "=r"(r) : "f"(hi), "f"(lo));
    return r;
}
__device__ __forceinline__ uint32_t tf32c(float f) {
    uint32_t r;
    asm("cvt.rna.tf32.f32 %0, %1;" : "=r"(r) : "f"(f));
    return r;
}
__device__ __forceinline__ float ex2f(float x) {
    float y;
    asm("ex2.approx.f32 %0, %1;" : "=f"(y) : "f"(x));
    return y;
}
#define LDSM4(r0, r1, r2, r3, a) \
    asm volatile("ldmatrix.sync.aligned.m8n8.x4.shared.b16 {%0,%1,%2,%3}, [%4];" \
        : "=r"(r0), "=r"(r1), "=r"(r2), "=r"(r3) : "r"(a))
#define LDS64(r0, r1, a) \
    asm volatile("ld.shared.v2.u32 {%0,%1}, [%2];" : "=r"(r0), "=r"(r1) : "r"(a))
#define LDS32(r0, a) \
    asm volatile("ld.shared.u32 %0, [%1];" : "=r"(r0) : "r"(a))

#define CP_ASYNC16(dst, src) \
    asm volatile("cp.async.ca.shared.global [%0], [%1], 16;" :: "r"(dst), "l"(src) : "memory")
#define CP_COMMIT() asm volatile("cp.async.commit_group;" ::: "memory")
#define CP_WAIT0()  asm volatile("cp.async.wait_group 0;" ::: "memory")
#define CP_WAIT1()  asm volatile("cp.async.wait_group 1;" ::: "memory")

// m16n8k8 tf32 MMA, C = 0
#define MMAT32_Z(d, a0, a1, a2, a3, b0, b1) \
    asm volatile("mma.sync.aligned.m16n8k8.row.col.f32.tf32.tf32.f32 " \
        "{%0,%1,%2,%3}, {%4,%5,%6,%7}, {%8,%9}, {%10,%10,%10,%10};" \
        : "=f"((d)[0]), "=f"((d)[1]), "=f"((d)[2]), "=f"((d)[3]) \
        : "r"(a0), "r"(a1), "r"(a2), "r"(a3), "r"(b0), "r"(b1), "f"(0.f))
// m16n8k8 tf32 MMA, accumulate in place
#define MMAT32(d, a0, a1, a2, a3, b0, b1) \
    asm volatile("mma.sync.aligned.m16n8k8.row.col.f32.tf32.tf32.f32 " \
        "{%0,%1,%2,%3}, {%4,%5,%6,%7}, {%8,%9}, {%0,%1,%2,%3};" \
        : "+f"((d)[0]), "+f"((d)[1]), "+f"((d)[2]), "+f"((d)[3]) \
        : "r"(a0), "r"(a1), "r"(a2), "r"(a3), "r"(b0), "r"(b1))
// m16n8k16 bf16 MMA, accumulate in place
#define MMA16816(d, a0, a1, a2, a3, b0, b1) \
    asm volatile("mma.sync.aligned.m16n8k16.row.col.f32.bf16.bf16.f32 " \
        "{%0,%1,%2,%3}, {%4,%5,%6,%7}, {%8,%9}, {%0,%1,%2,%3};" \
        : "+f"((d)[0]), "+f"((d)[1]), "+f"((d)[2]), "+f"((d)[3]) \
        : "r"(a0), "r"(a1), "r"(a2), "r"(a3), "r"(b0), "r"(b1))

// ---------------------------------------------------------------------------
// Kernel 1: projections on tensor cores (tf32) — round-10 verbatim.
// ---------------------------------------------------------------------------
__global__ void __launch_bounds__(128, 4) proj_kernel(
    const float* __restrict__ x,
    const float* __restrict__ wq, const float* __restrict__ bq,
    const float* __restrict__ wk, const float* __restrict__ bk,
    const float* __restrict__ wv, const float* __restrict__ bv)
{
    __shared__ __align__(16) char sx[64 * 272];
    __shared__ __align__(16) char sw[80 * 288];

    const int tid  = threadIdx.x;
    const int lane = tid & 31;
    const int w    = tid >> 5;
    const int g    = lane >> 2;
    const int t4   = lane & 3;
    const int b    = blockIdx.y;
    const int n0   = blockIdx.x * 64;

    const uint32_t sxb = smem_u32(sx);
    const uint32_t swb = smem_u32(sw);

    const float* xb = x + (size_t)b * CC * NN + n0;
    #pragma unroll
    for (int i = 0; i < 8; ++i) {
        const int c = i * 128 + tid;
        const int row = c >> 4, off = c & 15;
        CP_ASYNC16(sxb + row * 272 + off * 16, xb + (size_t)row * NN + off * 4);
    }
    #pragma unroll
    for (int i = 0; i < 8; ++i) {
        const int c = i * 128 + tid;
        const int row = c >> 4, off = c & 15;
        CP_ASYNC16(swb + row * 288 + off * 16, wv + row * 64 + off * 4);
    }
    {
        const int row = tid >> 4, off = tid & 15;
        CP_ASYNC16(swb + (64 + row) * 288 + off * 16, wq + row * 64 + off * 4);
        CP_ASYNC16(swb + (72 + row) * 288 + off * 16, wk + row * 64 + off * 4);
    }
    CP_COMMIT();

    float acc[2][5][4];
    #pragma unroll
    for (int mt = 0; mt < 4; ++mt) {
        const float bA = __ldg(bv + mt * 16 + g);
        const float bB = __ldg(bv + mt * 16 + 8 + g);
        #pragma unroll
        for (int n2 = 0; n2 < 2; ++n2) {
            acc[n2][mt][0] = bA; acc[n2][mt][1] = bA;
            acc[n2][mt][2] = bB; acc[n2][mt][3] = bB;
        }
    }
    {
        const float bA = __ldg(bq + g);
        const float bB = __ldg(bk + g);
        #pragma unroll
        for (int n2 = 0; n2 < 2; ++n2) {
            acc[n2][4][0] = bA; acc[n2][4][1] = bA;
            acc[n2][4][2] = bB; acc[n2][4][3] = bB;
        }
    }

    CP_WAIT0();
    __syncthreads();

    const uint32_t waddr0 = swb + (uint32_t)g * 288 + (uint32_t)t4 * 8;
    const uint32_t xaddr0 = sxb + (uint32_t)(2 * t4) * 272
                          + (uint32_t)((w * 2) * 8 + g) * 4;
    #pragma unroll
    for (int kt = 0; kt < 8; ++kt) {
        uint32_t wa[5][4];
        #pragma unroll
        for (int mt = 0; mt < 5; ++mt) {
            LDS64(wa[mt][0], wa[mt][2], waddr0 + (uint32_t)(mt * 16) * 288 + kt * 32);
            LDS64(wa[mt][1], wa[mt][3], waddr0 + (uint32_t)(mt * 16 + 8) * 288 + kt * 32);
        }
        #pragma unroll
        for (int mt = 0; mt < 5; ++mt) {
            #pragma unroll
            for (int e = 0; e < 4; ++e) wa[mt][e] = tf32c(__uint_as_float(wa[mt][e]));
        }
        #pragma unroll
        for (int n2 = 0; n2 < 2; ++n2) {
            uint32_t b0, b1;
            LDS32(b0, xaddr0 + kt * (8 * 272) + n2 * 32);
            LDS32(b1, xaddr0 + kt * (8 * 272) + n2 * 32 + 272);
            b0 = tf32c(__uint_as_float(b0));
            b1 = tf32c(__uint_as_float(b1));
            #pragma unroll
            for (int mt = 0; mt < 5; ++mt)
                MMAT32(acc[n2][mt], wa[mt][0], wa[mt][1], wa[mt][2], wa[mt][3], b0, b1);
        }
    }

    const int kslot = 2 * (g & 3) + (g >> 2);
    #pragma unroll
    for (int n2 = 0; n2 < 2; ++n2) {
        const int px = (w * 2 + n2) * 8 + 2 * t4;
        #pragma unroll
        for (int mt = 0; mt < 4; ++mt) {
            const int coA = mt * 16 + g;
            const int coB = coA + 8;
            *(uint32_t*)(g_Vb + (size_t)b * CC * NN + (size_t)coA * NN + n0 + px) =
                packbf(acc[n2][mt][0], acc[n2][mt][1]);
            *(uint32_t*)(g_Vb + (size_t)b * CC * NN + (size_t)coB * NN + n0 + px) =
                packbf(acc[n2][mt][2], acc[n2][mt][3]);
        }
        const size_t base0 = ((size_t)b * NN + n0 + px) * CQ;
        const size_t base1 = base0 + CQ;
        g_Q[base0 + g] = acc[n2][4][0] * LOG2E;
        g_Q[base1 + g] = acc[n2][4][1] * LOG2E;
        g_Kt[base0 + kslot] = tf32c(acc[n2][4][2]);
        g_Kt[base1 + kslot] = tf32c(acc[n2][4][3]);
    }
}

// ---------------------------------------------------------------------------
// Kernel 2: fused attention, warp-M=32 (2 m-tiles/warp), split-K 4.
// Block = 128 thr = 4 warps x 32 query rows = 128 queries.
// grid (32, 8, 4) = 1024 CTAs; each covers 1024 keys = 16 tiles of 64.
// Writes UNNORMALIZED partials g_P[s] + row sums g_L[s].
// smem: K 3 stages x 2KB | V 3 stages x 8KB = 30 KB. occ 3.
// ---------------------------------------------------------------------------
__global__ void __launch_bounds__(128, 3) attn_kernel()
{
    __shared__ __align__(16) char smraw[6144 + 3 * 8192];

    const int tid  = threadIdx.x;
    const int lane = tid & 31;
    const int w    = tid >> 5;
    const int g    = lane >> 2;
    const int t4   = lane & 3;
    const int b    = blockIdx.y;
    const int s    = blockIdx.z;
    const int ibase = blockIdx.x * 128 + w * 32;

    const uint32_t smb = smem_u32(smraw);

    // Q A-fragments for 2 m-tiles (rows ibase+mt*16+{g, g+8})
    const float* Qb = g_Q + (size_t)b * NN * CQ;
    uint32_t qa[2][4];
    #pragma unroll
    for (int mt = 0; mt < 2; ++mt) {
        const float* q0p = Qb + (size_t)(ibase + mt * 16 + g) * CQ;
        const float* q1p = Qb + (size_t)(ibase + mt * 16 + g + 8) * CQ;
        qa[mt][0] = tf32c(q0p[t4]);
        qa[mt][1] = tf32c(q1p[t4]);
        qa[mt][2] = tf32c(q0p[t4 + 4]);
        qa[mt][3] = tf32c(q1p[t4 + 4]);
    }

    // K staging (split-shifted): 128 threads x 16B = 2KB/tile
    const uint32_t* Ksrc = g_Kt + (size_t)b * NN * CQ + (size_t)s * KEYS_PER_SPLIT * CQ
                         + (size_t)(tid >> 1) * 8 + (tid & 1) * 4;
    const uint32_t kdst = smb + (uint32_t)(tid >> 1) * 32 + (uint32_t)(tid & 1) * 16;

    // V staging (split-shifted): 4 x 16B per tile, xor-swizzled rows
    const char* Vgb = (const char*)(g_Vb + (size_t)b * CC * NN);
    const uint32_t voff0 = (uint32_t)(tid >> 3) * (NN * 2) + (uint32_t)(tid & 7) * 16
                         + (uint32_t)s * (KEYS_PER_SPLIT * 2);
    const uint32_t vdst0 = smb + 6144 + (uint32_t)(tid >> 3) * 128
                         + (uint32_t)(((tid & 7) ^ ((tid >> 3) & 7)) << 4);

    // Score B-fragment LDS address (lane-only; shared by both m-tiles)
    const uint32_t kfrag0 = smb + (uint32_t)(lane >> 2) * 32 + (uint32_t)t4 * 8;

    // V ldmatrix addresses
    const int mat = lane >> 3, mrow = lane & 7, m01 = mat & 1;
    const uint32_t vbase0 = smb + 6144 + (uint32_t)((mat >> 1) * 8 + mrow) * 128;

    // Prologue: tiles 0, 1 of this split
    #pragma unroll
    for (int t = 0; t < 2; ++t) {
        CP_ASYNC16(kdst + t * 2048, Ksrc + (size_t)t * KT * CQ);
        #pragma unroll
        for (int r = 0; r < 4; ++r)
            CP_ASYNC16(vdst0 + r * 2048 + t * 8192, Vgb + voff0 + r * 131072 + t * 128);
        CP_COMMIT();
    }

    float acc[2][8][4];
    #pragma unroll
    for (int mt = 0; mt < 2; ++mt)
        #pragma unroll
        for (int nb = 0; nb < 8; ++nb)
            #pragma unroll
            for (int e = 0; e < 4; ++e) acc[mt][nb][e] = 0.f;
    float lsum[4] = {0.f, 0.f, 0.f, 0.f};   // [mt*2 + rowhalf]
    uint32_t ksoff = 0, vsoff = 0;

    #pragma unroll 1
    for (int t = 0; t < TILES_PER_SPLIT; ++t) {
        CP_WAIT1();
        __syncthreads();

        // Prefetch tile t+2 into stage (t+2)%3
        {
            const int tc = t + 2;
            uint32_t ks2 = ksoff + 4096;  if (ks2 >= 6144)  ks2 -= 6144;
            uint32_t vs2 = vsoff + 16384; if (vs2 >= 24576) vs2 -= 24576;
            if (tc < TILES_PER_SPLIT) {
                CP_ASYNC16(kdst + ks2, Ksrc + (size_t)tc * KT * CQ);
                #pragma unroll
                for (int r = 0; r < 4; ++r)
                    CP_ASYNC16(vdst0 + r * 2048 + vs2,
                               Vgb + voff0 + r * 131072 + (size_t)tc * 128);
            }
            CP_COMMIT();
        }

        #pragma unroll
        for (int kt = 0; kt < 4; ++kt) {
            // K b-fragments (shared by both m-tiles)
            uint32_t b00, b01, b10, b11;
            LDS64(b00, b01, kfrag0 + ksoff + (uint32_t)(2 * kt) * 256);
            LDS64(b10, b11, kfrag0 + ksoff + (uint32_t)(2 * kt) * 256 + 256);

            // Scores for 2 m-tiles x 2 n-tiles
            float p[2][2][4];
            #pragma unroll
            for (int mt = 0; mt < 2; ++mt) {
                MMAT32_Z(p[mt][0], qa[mt][0], qa[mt][1], qa[mt][2], qa[mt][3], b00, b01);
                MMAT32_Z(p[mt][1], qa[mt][0], qa[mt][1], qa[mt][2], qa[mt][3], b10, b11);
            }
            #pragma unroll
            for (int mt = 0; mt < 2; ++mt) {
                #pragma unroll
                for (int e = 0; e < 4; ++e) {
                    p[mt][0][e] = ex2f(p[mt][0][e]);
                    p[mt][1][e] = ex2f(p[mt][1][e]);
                }
                lsum[2 * mt + 0] += (p[mt][0][0] + p[mt][0][1]) + (p[mt][1][0] + p[mt][1][1]);
                lsum[2 * mt + 1] += (p[mt][0][2] + p[mt][0][3]) + (p[mt][1][2] + p[mt][1][3]);
            }

            // A-fragments
            uint32_t a[2][4];
            #pragma unroll
            for (int mt = 0; mt < 2; ++mt) {
                a[mt][0] = packbf(p[mt][0][0], p[mt][0][1]);
                a[mt][1] = packbf(p[mt][0][2], p[mt][0][3]);
                a[mt][2] = packbf(p[mt][1][0], p[mt][1][1]);
                a[mt][3] = packbf(p[mt][1][2], p[mt][1][3]);
            }

            // V b-fragments (shared by both m-tiles)
            const uint32_t term = ((uint32_t)((2 * kt + m01) ^ mrow)) << 4;
            uint32_t vb[16];
            #pragma unroll
            for (int c = 0; c < 4; ++c)
                LDSM4(vb[4 * c + 0], vb[4 * c + 1], vb[4 * c + 2], vb[4 * c + 3],
                      vbase0 + vsoff + c * 2048 + term);
            #pragma unroll
            for (int mt = 0; mt < 2; ++mt)
                #pragma unroll
                for (int nb = 0; nb < 8; ++nb)
                    MMA16816(acc[mt][nb], a[mt][0], a[mt][1], a[mt][2], a[mt][3],
                             vb[2 * nb], vb[2 * nb + 1]);
        }

        ksoff += 2048; if (ksoff == 6144)  ksoff = 0;
        vsoff += 8192; if (vsoff == 24576) vsoff = 0;
    }

    // Reduce l over the 4 lanes of each quad
    #pragma unroll
    for (int r = 0; r < 4; ++r) {
        lsum[r] += __shfl_xor_sync(0xFFFFFFFFu, lsum[r], 1);
        lsum[r] += __shfl_xor_sync(0xFFFFFFFFu, lsum[r], 2);
    }

    // Write unnormalized partials
    float* Pb = g_P + ((size_t)(s * BB + b) * CC) * NN;
    #pragma unroll
    for (int mt = 0; mt < 2; ++mt) {
        const int rA = ibase + mt * 16 + g;
        const int rB = rA + 8;
        #pragma unroll
        for (int nb = 0; nb < 8; ++nb) {
            const int c = nb * 8 + 2 * t4;
            Pb[(size_t)c * NN + rA]       = acc[mt][nb][0];
            Pb[(size_t)(c + 1) * NN + rA] = acc[mt][nb][1];
            Pb[(size_t)c * NN + rB]       = acc[mt][nb][2];
            Pb[(size_t)(c + 1) * NN + rB] = acc[mt][nb][3];
        }
    }
    if (t4 == 0) {
        float* Lb = g_L + (size_t)(s * BB + b) * NN;
        #pragma unroll
        for (int mt = 0; mt < 2; ++mt) {
            Lb[ibase + mt * 16 + g]     = lsum[2 * mt + 0];
            Lb[ibase + mt * 16 + g + 8] = lsum[2 * mt + 1];
        }
    }
}

// ---------------------------------------------------------------------------
// Kernel 3: combine split-K partials. out = sum_s P_s / sum_s L_s.
// 524288 float4 threads -> 2048 blocks x 256.
// ---------------------------------------------------------------------------
__global__ void __launch_bounds__(256) reduce_kernel(float* __restrict__ out)
{
    const int idx = blockIdx.x * 256 + threadIdx.x;   // float4 index
    const int i4  = idx & 1023;                       // 4096/4 per (b,c) row
    const int bc  = idx >> 10;                        // b*64 + c
    const int b   = bc >> 6;

    const float4* P4 = (const float4*)g_P;
    const float4* L4 = (const float4*)g_L;

    float4 ps = make_float4(0.f, 0.f, 0.f, 0.f);
    float4 ls = make_float4(0.f, 0.f, 0.f, 0.f);
    #pragma unroll
    for (int s = 0; s < NSPLIT; ++s) {
        const float4 p = P4[(size_t)(s * (BB * CC) + bc) * 1024 + i4];
        const float4 l = L4[(size_t)(s * BB + b) * 1024 + i4];
        ps.x += p.x; ps.y += p.y; ps.z += p.z; ps.w += p.w;
        ls.x += l.x; ls.y += l.y; ls.z += l.z; ls.w += l.w;
    }
    float4 o;
    o.x = ps.x / ls.x;
    o.y = ps.y / ls.y;
    o.z = ps.z / ls.z;
    o.w = ps.w / ls.w;
    ((float4*)out)[(size_t)bc * 1024 + i4] = o;
}

// ---------------------------------------------------------------------------
extern "C" void kernel_launch(void* const* d_in, const int* in_sizes, int n_in,
                              void* d_out, int out_size)
{
    const float* x  = (const float*)d_in[0];
    const float* wq = (const float*)d_in[1];
    const float* bq = (const float*)d_in[2];
    const float* wk = (const float*)d_in[3];
    const float* bk = (const float*)d_in[4];
    const float* wv = (const float*)d_in[5];
    const float* bv = (const float*)d_in[6];
    float* out = (float*)d_out;

    dim3 pgrid(NN / 64, BB);
    proj_kernel<<<pgrid, 128>>>(x, wq, bq, wk, bk, wv, bv);

    dim3 agrid(NN / 128, BB, NSPLIT);
    attn_kernel<<<agrid, 128>>>();

    reduce_kernel<<<2048, 256>>>(out);
}

// round 12
// speedup vs baseline: 1.8561x; 1.1018x over previous
#include <cuda_runtime.h>
#include <cuda_fp16.h>
#include <cstdint>

#define BB 8
#define CC 64
#define CQ 8
#define NN 4096
#define KT 64
#define NSPLIT 4
#define KEYS_PER_SPLIT (NN / NSPLIT)          // 1024
#define TILES_PER_SPLIT (KEYS_PER_SPLIT / KT) // 16
#define LOG2E 1.4426950408889634f

// Device scratch (allocation-free rule)
__device__ float    g_Q[BB * NN * CQ];          // [b][n][cq] f32, pre-scaled by log2e
__device__ uint32_t g_Kt[BB * NN * CQ];         // [b][n]: 8 tf32 bits, pair-permuted (c,c+4)
__device__ __half   g_Vh[BB * CC * NN];         // [b][c][n] fp16 (V^T)
__device__ float    g_P[NSPLIT * BB * CC * NN]; // [s][b][c][i] unnormalized partials
__device__ float    g_L[NSPLIT * BB * NN];      // [s][b][i] partial row sums

// ---------------------------------------------------------------------------
// PTX helpers (baseline compute_103-safe)
// ---------------------------------------------------------------------------
__device__ __forceinline__ uint32_t smem_u32(const void* p) {
    uint32_t a;
    asm("{ .reg .u64 t; cvta.to.shared.u64 t, %1; cvt.u32.u64 %0, t; }" : "=r"(a) : "l"(p));
    return a;
}
__device__ __forceinline__ uint32_t packh(float lo, float hi) {   // f16x2 {hi|lo}
    uint32_t r;
    asm("cvt.rn.f16x2.f32 %0, %1, %2;" : "=r"(r) : "f"(hi), "f"(lo));
    return r;
}
__device__ __forceinline__ uint32_t ex2h2(uint32_t x) {           // packed f16x2 exp2
    uint32_t y;
    asm("ex2.approx.f16x2 %0, %1;" : "=r"(y) : "r"(x));
    return y;
}
__device__ __forceinline__ uint32_t tf32c(float f) {
    uint32_t r;
    asm("cvt.rna.tf32.f32 %0, %1;" : "=r"(r) : "f"(f));
    return r;
}
#define LDSM4(r0, r1, r2, r3, a) \
    asm volatile("ldmatrix.sync.aligned.m8n8.x4.shared.b16 {%0,%1,%2,%3}, [%4];" \
        : "=r"(r0), "=r"(r1), "=r"(r2), "=r"(r3) : "r"(a))
#define LDS64(r0, r1, a) \
    asm volatile("ld.shared.v2.u32 {%0,%1}, [%2];" : "=r"(r0), "=r"(r1) : "r"(a))
#define LDS32(r0, a) \
    asm volatile("ld.shared.u32 %0, [%1];" : "=r"(r0) : "r"(a))

#define CP_ASYNC16(dst, src) \
    asm volatile("cp.async.ca.shared.global [%0], [%1], 16;" :: "r"(dst), "l"(src) : "memory")
#define CP_COMMIT() asm volatile("cp.async.commit_group;" ::: "memory")
#define CP_WAIT0()  asm volatile("cp.async.wait_group 0;" ::: "memory")
#define CP_WAIT1()  asm volatile("cp.async.wait_group 1;" ::: "memory")

// m16n8k8 tf32 MMA, C = 0
#define MMAT32_Z(d, a0, a1, a2, a3, b0, b1) \
    asm volatile("mma.sync.aligned.m16n8k8.row.col.f32.tf32.tf32.f32 " \
        "{%0,%1,%2,%3}, {%4,%5,%6,%7}, {%8,%9}, {%10,%10,%10,%10};" \
        : "=f"((d)[0]), "=f"((d)[1]), "=f"((d)[2]), "=f"((d)[3]) \
        : "r"(a0), "r"(a1), "r"(a2), "r"(a3), "r"(b0), "r"(b1), "f"(0.f))
// m16n8k8 tf32 MMA, accumulate in place
#define MMAT32(d, a0, a1, a2, a3, b0, b1) \
    asm volatile("mma.sync.aligned.m16n8k8.row.col.f32.tf32.tf32.f32 " \
        "{%0,%1,%2,%3}, {%4,%5,%6,%7}, {%8,%9}, {%0,%1,%2,%3};" \
        : "+f"((d)[0]), "+f"((d)[1]), "+f"((d)[2]), "+f"((d)[3]) \
        : "r"(a0), "r"(a1), "r"(a2), "r"(a3), "r"(b0), "r"(b1))
// m16n8k16 fp16 MMA (f32 accum), accumulate in place
#define MMAH16(d, a0, a1, a2, a3, b0, b1) \
    asm volatile("mma.sync.aligned.m16n8k16.row.col.f32.f16.f16.f32 " \
        "{%0,%1,%2,%3}, {%4,%5,%6,%7}, {%8,%9}, {%0,%1,%2,%3};" \
        : "+f"((d)[0]), "+f"((d)[1]), "+f"((d)[2]), "+f"((d)[3]) \
        : "r"(a0), "r"(a1), "r"(a2), "r"(a3), "r"(b0), "r"(b1))

// ---------------------------------------------------------------------------
// Kernel 1: projections on tensor cores (tf32) — round-10 core; V now fp16.
// ---------------------------------------------------------------------------
__global__ void __launch_bounds__(128, 4) proj_kernel(
    const float* __restrict__ x,
    const float* __restrict__ wq, const float* __restrict__ bq,
    const float* __restrict__ wk, const float* __restrict__ bk,
    const float* __restrict__ wv, const float* __restrict__ bv)
{
    __shared__ __align__(16) char sx[64 * 272];
    __shared__ __align__(16) char sw[80 * 288];

    const int tid  = threadIdx.x;
    const int lane = tid & 31;
    const int w    = tid >> 5;
    const int g    = lane >> 2;
    const int t4   = lane & 3;
    const int b    = blockIdx.y;
    const int n0   = blockIdx.x * 64;

    const uint32_t sxb = smem_u32(sx);
    const uint32_t swb = smem_u32(sw);

    const float* xb = x + (size_t)b * CC * NN + n0;
    #pragma unroll
    for (int i = 0; i < 8; ++i) {
        const int c = i * 128 + tid;
        const int row = c >> 4, off = c & 15;
        CP_ASYNC16(sxb + row * 272 + off * 16, xb + (size_t)row * NN + off * 4);
    }
    #pragma unroll
    for (int i = 0; i < 8; ++i) {
        const int c = i * 128 + tid;
        const int row = c >> 4, off = c & 15;
        CP_ASYNC16(swb + row * 288 + off * 16, wv + row * 64 + off * 4);
    }
    {
        const int row = tid >> 4, off = tid & 15;
        CP_ASYNC16(swb + (64 + row) * 288 + off * 16, wq + row * 64 + off * 4);
        CP_ASYNC16(swb + (72 + row) * 288 + off * 16, wk + row * 64 + off * 4);
    }
    CP_COMMIT();

    float acc[2][5][4];
    #pragma unroll
    for (int mt = 0; mt < 4; ++mt) {
        const float bA = __ldg(bv + mt * 16 + g);
        const float bB = __ldg(bv + mt * 16 + 8 + g);
        #pragma unroll
        for (int n2 = 0; n2 < 2; ++n2) {
            acc[n2][mt][0] = bA; acc[n2][mt][1] = bA;
            acc[n2][mt][2] = bB; acc[n2][mt][3] = bB;
        }
    }
    {
        const float bA = __ldg(bq + g);
        const float bB = __ldg(bk + g);
        #pragma unroll
        for (int n2 = 0; n2 < 2; ++n2) {
            acc[n2][4][0] = bA; acc[n2][4][1] = bA;
            acc[n2][4][2] = bB; acc[n2][4][3] = bB;
        }
    }

    CP_WAIT0();
    __syncthreads();

    const uint32_t waddr0 = swb + (uint32_t)g * 288 + (uint32_t)t4 * 8;
    const uint32_t xaddr0 = sxb + (uint32_t)(2 * t4) * 272
                          + (uint32_t)((w * 2) * 8 + g) * 4;
    #pragma unroll
    for (int kt = 0; kt < 8; ++kt) {
        uint32_t wa[5][4];
        #pragma unroll
        for (int mt = 0; mt < 5; ++mt) {
            LDS64(wa[mt][0], wa[mt][2], waddr0 + (uint32_t)(mt * 16) * 288 + kt * 32);
            LDS64(wa[mt][1], wa[mt][3], waddr0 + (uint32_t)(mt * 16 + 8) * 288 + kt * 32);
        }
        #pragma unroll
        for (int mt = 0; mt < 5; ++mt) {
            #pragma unroll
            for (int e = 0; e < 4; ++e) wa[mt][e] = tf32c(__uint_as_float(wa[mt][e]));
        }
        #pragma unroll
        for (int n2 = 0; n2 < 2; ++n2) {
            uint32_t b0, b1;
            LDS32(b0, xaddr0 + kt * (8 * 272) + n2 * 32);
            LDS32(b1, xaddr0 + kt * (8 * 272) + n2 * 32 + 272);
            b0 = tf32c(__uint_as_float(b0));
            b1 = tf32c(__uint_as_float(b1));
            #pragma unroll
            for (int mt = 0; mt < 5; ++mt)
                MMAT32(acc[n2][mt], wa[mt][0], wa[mt][1], wa[mt][2], wa[mt][3], b0, b1);
        }
    }

    const int kslot = 2 * (g & 3) + (g >> 2);
    #pragma unroll
    for (int n2 = 0; n2 < 2; ++n2) {
        const int px = (w * 2 + n2) * 8 + 2 * t4;
        #pragma unroll
        for (int mt = 0; mt < 4; ++mt) {
            const int coA = mt * 16 + g;
            const int coB = coA + 8;
            *(uint32_t*)(g_Vh + (size_t)b * CC * NN + (size_t)coA * NN + n0 + px) =
                packh(acc[n2][mt][0], acc[n2][mt][1]);
            *(uint32_t*)(g_Vh + (size_t)b * CC * NN + (size_t)coB * NN + n0 + px) =
                packh(acc[n2][mt][2], acc[n2][mt][3]);
        }
        const size_t base0 = ((size_t)b * NN + n0 + px) * CQ;
        const size_t base1 = base0 + CQ;
        g_Q[base0 + g] = acc[n2][4][0] * LOG2E;
        g_Q[base1 + g] = acc[n2][4][1] * LOG2E;
        g_Kt[base0 + kslot] = tf32c(acc[n2][4][2]);
        g_Kt[base1 + kslot] = tf32c(acc[n2][4][3]);
    }
}

// ---------------------------------------------------------------------------
// Kernel 2: fused attention, warp-M=32, split-K 4, fp16 PV + packed f16 exp.
// l via ones-column f16 MMA (exact f32 row sums, no shuffles).
// ---------------------------------------------------------------------------
__global__ void __launch_bounds__(128, 3) attn_kernel()
{
    __shared__ __align__(16) char smraw[6144 + 3 * 8192];

    const int tid  = threadIdx.x;
    const int lane = tid & 31;
    const int w    = tid >> 5;
    const int g    = lane >> 2;
    const int t4   = lane & 3;
    const int b    = blockIdx.y;
    const int s    = blockIdx.z;
    const int ibase = blockIdx.x * 128 + w * 32;

    const uint32_t smb = smem_u32(smraw);
    const uint32_t ONESH = 0x3C003C00u;       // f16x2 {1.0, 1.0}

    // Q A-fragments for 2 m-tiles
    const float* Qb = g_Q + (size_t)b * NN * CQ;
    uint32_t qa[2][4];
    #pragma unroll
    for (int mt = 0; mt < 2; ++mt) {
        const float* q0p = Qb + (size_t)(ibase + mt * 16 + g) * CQ;
        const float* q1p = Qb + (size_t)(ibase + mt * 16 + g + 8) * CQ;
        qa[mt][0] = tf32c(q0p[t4]);
        qa[mt][1] = tf32c(q1p[t4]);
        qa[mt][2] = tf32c(q0p[t4 + 4]);
        qa[mt][3] = tf32c(q1p[t4 + 4]);
    }

    // K staging (split-shifted)
    const uint32_t* Ksrc = g_Kt + (size_t)b * NN * CQ + (size_t)s * KEYS_PER_SPLIT * CQ
                         + (size_t)(tid >> 1) * 8 + (tid & 1) * 4;
    const uint32_t kdst = smb + (uint32_t)(tid >> 1) * 32 + (uint32_t)(tid & 1) * 16;

    // V staging (split-shifted)
    const char* Vgb = (const char*)(g_Vh + (size_t)b * CC * NN);
    const uint32_t voff0 = (uint32_t)(tid >> 3) * (NN * 2) + (uint32_t)(tid & 7) * 16
                         + (uint32_t)s * (KEYS_PER_SPLIT * 2);
    const uint32_t vdst0 = smb + 6144 + (uint32_t)(tid >> 3) * 128
                         + (uint32_t)(((tid & 7) ^ ((tid >> 3) & 7)) << 4);

    // Score B-fragment LDS address
    const uint32_t kfrag0 = smb + (uint32_t)(lane >> 2) * 32 + (uint32_t)t4 * 8;

    // V ldmatrix addresses
    const int mat = lane >> 3, mrow = lane & 7, m01 = mat & 1;
    const uint32_t vbase0 = smb + 6144 + (uint32_t)((mat >> 1) * 8 + mrow) * 128;

    // Prologue: tiles 0, 1 of this split
    #pragma unroll
    for (int t = 0; t < 2; ++t) {
        CP_ASYNC16(kdst + t * 2048, Ksrc + (size_t)t * KT * CQ);
        #pragma unroll
        for (int r = 0; r < 4; ++r)
            CP_ASYNC16(vdst0 + r * 2048 + t * 8192, Vgb + voff0 + r * 131072 + t * 128);
        CP_COMMIT();
    }

    float acc[2][8][4];
    #pragma unroll
    for (int mt = 0; mt < 2; ++mt)
        #pragma unroll
        for (int nb = 0; nb < 8; ++nb)
            #pragma unroll
            for (int e = 0; e < 4; ++e) acc[mt][nb][e] = 0.f;
    float lacc[2][4];
    #pragma unroll
    for (int mt = 0; mt < 2; ++mt)
        #pragma unroll
        for (int e = 0; e < 4; ++e) lacc[mt][e] = 0.f;
    uint32_t ksoff = 0, vsoff = 0;

    #pragma unroll 1
    for (int t = 0; t < TILES_PER_SPLIT; ++t) {
        CP_WAIT1();
        __syncthreads();

        // Prefetch tile t+2
        {
            const int tc = t + 2;
            uint32_t ks2 = ksoff + 4096;  if (ks2 >= 6144)  ks2 -= 6144;
            uint32_t vs2 = vsoff + 16384; if (vs2 >= 24576) vs2 -= 24576;
            if (tc < TILES_PER_SPLIT) {
                CP_ASYNC16(kdst + ks2, Ksrc + (size_t)tc * KT * CQ);
                #pragma unroll
                for (int r = 0; r < 4; ++r)
                    CP_ASYNC16(vdst0 + r * 2048 + vs2,
                               Vgb + voff0 + r * 131072 + (size_t)tc * 128);
            }
            CP_COMMIT();
        }

        #pragma unroll
        for (int kt = 0; kt < 4; ++kt) {
            // K b-fragments (shared by both m-tiles)
            uint32_t b00, b01, b10, b11;
            LDS64(b00, b01, kfrag0 + ksoff + (uint32_t)(2 * kt) * 256);
            LDS64(b10, b11, kfrag0 + ksoff + (uint32_t)(2 * kt) * 256 + 256);

            // Scores for 2 m-tiles x 2 n-tiles
            float p[2][2][4];
            #pragma unroll
            for (int mt = 0; mt < 2; ++mt) {
                MMAT32_Z(p[mt][0], qa[mt][0], qa[mt][1], qa[mt][2], qa[mt][3], b00, b01);
                MMAT32_Z(p[mt][1], qa[mt][0], qa[mt][1], qa[mt][2], qa[mt][3], b10, b11);
            }

            // Pack score pairs to f16x2, packed exp2 -> A-fragments directly
            uint32_t a[2][4];
            #pragma unroll
            for (int mt = 0; mt < 2; ++mt) {
                a[mt][0] = ex2h2(packh(p[mt][0][0], p[mt][0][1]));
                a[mt][1] = ex2h2(packh(p[mt][0][2], p[mt][0][3]));
                a[mt][2] = ex2h2(packh(p[mt][1][0], p[mt][1][1]));
                a[mt][3] = ex2h2(packh(p[mt][1][2], p[mt][1][3]));
            }

            // V b-fragments (shared by both m-tiles)
            const uint32_t term = ((uint32_t)((2 * kt + m01) ^ mrow)) << 4;
            uint32_t vb[16];
            #pragma unroll
            for (int c = 0; c < 4; ++c)
                LDSM4(vb[4 * c + 0], vb[4 * c + 1], vb[4 * c + 2], vb[4 * c + 3],
                      vbase0 + vsoff + c * 2048 + term);
            #pragma unroll
            for (int mt = 0; mt < 2; ++mt) {
                #pragma unroll
                for (int nb = 0; nb < 8; ++nb)
                    MMAH16(acc[mt][nb], a[mt][0], a[mt][1], a[mt][2], a[mt][3],
                           vb[2 * nb], vb[2 * nb + 1]);
                // l row-sums: B = ones (exact f32 accumulation on tensor pipe)
                MMAH16(lacc[mt], a[mt][0], a[mt][1], a[mt][2], a[mt][3], ONESH, ONESH);
            }
        }

        ksoff += 2048; if (ksoff == 6144)  ksoff = 0;
        vsoff += 8192; if (vsoff == 24576) vsoff = 0;
    }

    // Write unnormalized partials
    float* Pb = g_P + ((size_t)(s * BB + b) * CC) * NN;
    #pragma unroll
    for (int mt = 0; mt < 2; ++mt) {
        const int rA = ibase + mt * 16 + g;
        const int rB = rA + 8;
        #pragma unroll
        for (int nb = 0; nb < 8; ++nb) {
            const int c = nb * 8 + 2 * t4;
            Pb[(size_t)c * NN + rA]       = acc[mt][nb][0];
            Pb[(size_t)(c + 1) * NN + rA] = acc[mt][nb][1];
            Pb[(size_t)c * NN + rB]       = acc[mt][nb][2];
            Pb[(size_t)(c + 1) * NN + rB] = acc[mt][nb][3];
        }
    }
    // lacc[mt][0] / [2] are the full row sums (same across the quad lanes)
    if (t4 == 0) {
        float* Lb = g_L + (size_t)(s * BB + b) * NN;
        #pragma unroll
        for (int mt = 0; mt < 2; ++mt) {
            Lb[ibase + mt * 16 + g]     = lacc[mt][0];
            Lb[ibase + mt * 16 + g + 8] = lacc[mt][2];
        }
    }
}

// ---------------------------------------------------------------------------
// Kernel 3: combine split-K partials. out = sum_s P_s / sum_s L_s.
// ---------------------------------------------------------------------------
__global__ void __launch_bounds__(256) reduce_kernel(float* __restrict__ out)
{
    const int idx = blockIdx.x * 256 + threadIdx.x;
    const int i4  = idx & 1023;
    const int bc  = idx >> 10;
    const int b   = bc >> 6;

    const float4* P4 = (const float4*)g_P;
    const float4* L4 = (const float4*)g_L;

    float4 ps = make_float4(0.f, 0.f, 0.f, 0.f);
    float4 ls = make_float4(0.f, 0.f, 0.f, 0.f);
    #pragma unroll
    for (int s = 0; s < NSPLIT; ++s) {
        const float4 p = P4[(size_t)(s * (BB * CC) + bc) * 1024 + i4];
        const float4 l = L4[(size_t)(s * BB + b) * 1024 + i4];
        ps.x += p.x; ps.y += p.y; ps.z += p.z; ps.w += p.w;
        ls.x += l.x; ls.y += l.y; ls.z += l.z; ls.w += l.w;
    }
    float4 o;
    o.x = ps.x / ls.x;
    o.y = ps.y / ls.y;
    o.z = ps.z / ls.z;
    o.w = ps.w / ls.w;
    ((float4*)out)[(size_t)bc * 1024 + i4] = o;
}

// ---------------------------------------------------------------------------
extern "C" void kernel_launch(void* const* d_in, const int* in_sizes, int n_in,
                              void* d_out, int out_size)
{
    const float* x  = (const float*)d_in[0];
    const float* wq = (const float*)d_in[1];
    const float* bq = (const float*)d_in[2];
    const float* wk = (const float*)d_in[3];
    const float* bk = (const float*)d_in[4];
    const float* wv = (const float*)d_in[5];
    const float* bv = (const float*)d_in[6];
    float* out = (float*)d_out;

    dim3 pgrid(NN / 64, BB);
    proj_kernel<<<pgrid, 128>>>(x, wq, bq, wk, bk, wv, bv);

    dim3 agrid(NN / 128, BB, NSPLIT);
    attn_kernel<<<agrid, 128>>>();

    reduce_kernel<<<2048, 256>>>(out);
}